// round 13
// baseline (speedup 1.0000x reference)
#include <cuda_runtime.h>
#include <cuda_fp16.h>
#include <cstdint>

#define BATCH   64
#define SEQ     1024
#define IDIM    128
#define HDIM    512
#define G4      2048
#define KTOT    640
#define NGRP    4
#define GB      16
#define NCTA    32
#define HC      16
#define NL      64
#define THREADS 128
#define NCH_H   32
#define NCH_X   8
#define NCH     40

#define ZSTR    648
#define OFF_Z   0
#define SMEM_SZ (NL * ZSTR * 2)             // 82944 B : weights only

// ---- global scratch (static) -------------------------------------------------
__device__ uint32_t g_xfrag[(size_t)NGRP * SEQ * NCH_X * 128];  // x in frag layout
__device__ uint32_t g_hfrag[2 * NGRP * NCTA * 128];             // ping-pong h chunks
__device__ float    g_hfin[BATCH][HDIM];                        // exact final h
__device__ int      g_step[NGRP][32];                           // 128B-padded counter
__device__ int      g_cnt, g_gen;

// ---- prologue-only global barrier (replay-safe) ------------------------------
__device__ __forceinline__ void bar_all(int n)
{
    int my;
    asm volatile("ld.acquire.gpu.global.b32 %0, [%1];" : "=r"(my) : "l"(&g_gen));
    __threadfence();
    if (atomicAdd(&g_cnt, 1) == n - 1) {
        atomicExch(&g_cnt, 0);
        __threadfence();
        atomicAdd(&g_gen, 1);
    } else {
        int v;
        do { asm volatile("ld.acquire.gpu.global.b32 %0, [%1];" : "=r"(v) : "l"(&g_gen)); }
        while (v == my);
    }
}

// single-line poll (validated best in R6-R9)
__device__ __forceinline__ void poll_cnt(int g, int need)
{
    const int* p = &g_step[g][0];
    int v;
    do { asm volatile("ld.acquire.gpu.global.b32 %0, [%1];" : "=r"(v) : "l"(p)); }
    while (v < need);
}
__device__ __forceinline__ void release_inc(int g)
{
    asm volatile("red.add.release.gpu.global.s32 [%0], 1;" :: "l"(&g_step[g][0]) : "memory");
}

__device__ __forceinline__ void ldsm4(unsigned r[4], uint32_t a)
{
    asm volatile("ldmatrix.sync.aligned.m8n8.x4.shared.b16 {%0,%1,%2,%3}, [%4];"
                 : "=r"(r[0]), "=r"(r[1]), "=r"(r[2]), "=r"(r[3]) : "r"(a));
}
__device__ __forceinline__ void mma_f16(float* d, const unsigned* a, const unsigned* b)
{
    asm volatile(
        "mma.sync.aligned.m16n8k16.row.col.f32.f16.f16.f32 "
        "{%0,%1,%2,%3}, {%4,%5,%6,%7}, {%8,%9}, {%0,%1,%2,%3};\n"
        : "+f"(d[0]), "+f"(d[1]), "+f"(d[2]), "+f"(d[3])
        : "r"(a[0]), "r"(a[1]), "r"(a[2]), "r"(a[3]), "r"(b[0]), "r"(b[1]));
}

__device__ __forceinline__ float fsig(float x)  { return 1.f / (1.f + __expf(-x)); }
__device__ __forceinline__ float ftanh(float x) { return 1.f - 2.f / (__expf(2.f * x) + 1.f); }

// ---- x -> fp16 fragment-ready layout (validated) -----------------------------
extern "C" __global__ void xsplit_kernel(const float* __restrict__ x)
{
    int gid = blockIdx.x * 256 + threadIdx.x;
    int i0 = (gid & 31) * 4;
    int s  = (gid >> 5) & (SEQ - 1);
    int b  = gid >> 15;
    float4 v = *(const float4*)(x + ((size_t)b * SEQ + s) * IDIM + i0);
    int bl = b & 15, grp = b >> 4;
    int kx = i0 >> 4, kl = i0 & 15;
    int lane = ((bl & 7) << 2) | ((kl & 7) >> 1);
    int j    = ((kl >> 3) << 1) | (bl >> 3);
    uint32_t u0 = (uint32_t)__half_as_ushort(__float2half(v.x)) |
                  ((uint32_t)__half_as_ushort(__float2half(v.y)) << 16);
    uint32_t u1 = (uint32_t)__half_as_ushort(__float2half(v.z)) |
                  ((uint32_t)__half_as_ushort(__float2half(v.w)) << 16);
    size_t base = (((size_t)grp * SEQ + s) * NCH_X + kx) * 128;
    g_xfrag[base + lane * 4 + j]       = u0;
    g_xfrag[base + (lane + 1) * 4 + j] = u1;
}

// ---- persistent LSTM: R9 sync + direct-to-register h loads -------------------
extern "C" __global__ void __launch_bounds__(THREADS, 1)
lstm_kernel(const float* __restrict__ W, const float* __restrict__ U,
            const float* __restrict__ bias,
            const float* __restrict__ fc_w, const float* __restrict__ fc_b,
            float* __restrict__ out)
{
    extern __shared__ char smem[];
    __half* zh = (__half*)(smem + OFF_Z);

    const int tid  = threadIdx.x;
    const int lane = tid & 31;
    const int warp = tid >> 5;
    const int grp  = blockIdx.x >> 5;
    const int gc   = blockIdx.x & 31;
    const int b0   = grp * GB;
    const int h0   = gc * HC;
    const uint32_t smb = (uint32_t)__cvta_generic_to_shared(smem);

    // weights into smem, gate-interleaved local cols: nl -> hid=nl>>2, gate=nl&3
    for (int idx = tid; idx < KTOT * NL; idx += THREADS) {
        int k = idx >> 6, nl = idx & 63;
        int col = (nl & 3) * HDIM + h0 + (nl >> 2);
        float v = (k < HDIM) ? U[(size_t)k * G4 + col]
                             : W[(size_t)(k - HDIM) * G4 + col];
        zh[nl * ZSTR + k] = __float2half(v);
    }
    const int q = (lane >> 1) & 1;
    float bv[2][2];
    #pragma unroll
    for (int t = 0; t < 2; t++) {
        int hid = h0 + warp * 4 + t * 2 + q;
        #pragma unroll
        for (int j = 0; j < 2; j++)
            bv[t][j] = bias[(2 * (lane & 1) + j) * HDIM + hid];
    }
    if (tid == 0 && gc == 0) g_step[grp][0] = 0;   // replay-safe reset
    __syncthreads();

    // register-resident B fragments for the 32 h-chunks only (128 regs);
    // x-chunk B frags are re-read via ldsm each step (off critical path)
    const int brow = warp * 16 + ((lane & 7) | ((lane >> 1) & 8));
    const uint32_t bHiA = smb + OFF_Z + ((brow * ZSTR + (lane & 8)) << 1);
    unsigned bfr[NCH_H][4];
    #pragma unroll
    for (int kc = 0; kc < NCH_H; kc++)
        ldsm4(bfr[kc], bHiA + kc * 32);

    if (tid == 0) bar_all(NGRP * NCTA);
    __syncthreads();

    const int r = lane >> 2;
    const int jt_c = (warp >> 1) << 1;
    const int lt_c = (warp & 1) << 1;
    float c0 = 0.f, c1 = 0.f;

    for (int s = 0; s < SEQ; s++) {
        float accA[2][4], accB[2][4];
        #pragma unroll
        for (int t = 0; t < 2; t++) {
            accA[t][0] = bv[t][0]; accA[t][1] = bv[t][1];
            accA[t][2] = bv[t][0]; accA[t][3] = bv[t][1];
            accB[t][0] = 0.f; accB[t][1] = 0.f;
            accB[t][2] = 0.f; accB[t][3] = 0.f;
        }

        // x fragment loads (issued early; latency hidden behind the poll)
        uint32_t xv[NCH_X][4];
        {
            const uint4* xb = (const uint4*)(g_xfrag +
                (((size_t)grp * SEQ + s) * NCH_X) * 128 + lane * 4);
            #pragma unroll
            for (int kx = 0; kx < NCH_X; kx++) {
                uint4 t4 = __ldg(xb + kx * 32);
                xv[kx][0] = t4.x; xv[kx][1] = t4.y; xv[kx][2] = t4.z; xv[kx][3] = t4.w;
            }
        }

        const uint4* hs = (const uint4*)((const char*)g_hfrag +
            ((size_t)((s & 1) * NGRP + grp) * NCTA) * 512) + lane;

        uint4 wa[2][4];
        if (s > 0) {
            poll_cnt(grp, 128 * s);
            // wave 0 issue (acquire above orders these after producers' stores)
            #pragma unroll
            for (int i = 0; i < 4; i++)
                wa[0][i] = __ldcg(hs + i * 32);
        }

        // x-part GEMM (covers wave-0 LDG latency)
        #pragma unroll
        for (int kx = 0; kx < NCH_X; kx++) {
            unsigned bh[4];
            ldsm4(bh, bHiA + (NCH_H + kx) * 32);
            float* d0 = (kx & 1) ? accB[0] : accA[0];
            float* d1 = (kx & 1) ? accB[1] : accA[1];
            mma_f16(d0, xv[kx], bh);
            mma_f16(d1, xv[kx], bh + 2);
        }

        // h-part GEMM: 8 waves of 4 chunks, double-buffered direct LDG
        if (s > 0) {
            #pragma unroll
            for (int w = 0; w < 8; w++) {
                if (w < 7) {
                    #pragma unroll
                    for (int i = 0; i < 4; i++)
                        wa[(w + 1) & 1][i] = __ldcg(hs + (w * 4 + 4 + i) * 32);
                }
                #pragma unroll
                for (int i = 0; i < 4; i++) {
                    int kc = w * 4 + i;
                    const unsigned* av = (const unsigned*)&wa[w & 1][i];
                    float* d0 = (kc & 1) ? accB[0] : accA[0];
                    float* d1 = (kc & 1) ? accB[1] : accA[1];
                    mma_f16(d0, av, bfr[kc]);
                    mma_f16(d1, av, bfr[kc] + 2);
                }
            }
        }

        // register epilogue: combine chains, gate exchange, packed h store
        char* hdst = (char*)g_hfrag +
            ((size_t)(((s + 1) & 1) * NGRP + grp) * NCTA + gc) * 512;
        #pragma unroll
        for (int t = 0; t < 2; t++) {
            float a0 = accA[t][0] + accB[t][0];
            float a1 = accA[t][1] + accB[t][1];
            float a2 = accA[t][2] + accB[t][2];
            float a3 = accA[t][3] + accB[t][3];
            float e0 = __shfl_xor_sync(0xffffffffu, a0, 1);
            float e1 = __shfl_xor_sync(0xffffffffu, a1, 1);
            float e2 = __shfl_xor_sync(0xffffffffu, a2, 1);
            float e3 = __shfl_xor_sync(0xffffffffu, a3, 1);
            float gi, gf, gg, go;
            int bidx;
            if ((lane & 1) == 0) {
                gi = a0; gf = a1; gg = e0; go = e1; bidx = r;
            } else {
                gi = e2; gf = e3; gg = a2; go = a3; bidx = r + 8;
            }
            float i_ = fsig(gi), f_ = fsig(gf), g_ = ftanh(gg), o_ = fsig(go);
            float& cc = t ? c1 : c0;
            cc = f_ * cc + i_ * g_;
            float h = o_ * ftanh(cc);
            unsigned hb = (unsigned)__half_as_ushort(__float2half(h));
            unsigned ob = __shfl_xor_sync(0xffffffffu, hb, 2);
            if (q == 0) {
                unsigned word = hb | (ob << 16);
                int lt = ((bidx & 7) << 2) | lt_c | t;
                int jt = jt_c | (bidx >> 3);
                *(unsigned*)(hdst + lt * 16 + jt * 4) = word;
            }
            if (s == SEQ - 1) g_hfin[b0 + bidx][h0 + warp * 4 + t * 2 + q] = h;
        }
        if (lane == 0) release_inc(grp);
    }

    // FC head: one CTA per group, exact fp32 h
    if (gc == 0) {
        poll_cnt(grp, 128 * SEQ);
        int b = tid >> 3, l8 = tid & 7;
        float a7[7] = {0.f, 0.f, 0.f, 0.f, 0.f, 0.f, 0.f};
        for (int it = 0; it < HDIM / 8; it++) {
            int k = l8 + it * 8;
            float hv;
            asm volatile("ld.relaxed.gpu.global.f32 %0, [%1];"
                         : "=f"(hv) : "l"(&g_hfin[b0 + b][k]));
            #pragma unroll
            for (int o = 0; o < 7; o++) a7[o] += hv * fc_w[k * 7 + o];
        }
        #pragma unroll
        for (int o = 0; o < 7; o++) {
            a7[o] += __shfl_xor_sync(0xffffffffu, a7[o], 4);
            a7[o] += __shfl_xor_sync(0xffffffffu, a7[o], 2);
            a7[o] += __shfl_xor_sync(0xffffffffu, a7[o], 1);
        }
        if (l8 == 0)
            #pragma unroll
            for (int o = 0; o < 7; o++) out[(b0 + b) * 7 + o] = a7[o] + fc_b[o];
    }
}

extern "C" void kernel_launch(void* const* d_in, const int* in_sizes, int n_in,
                              void* d_out, int out_size)
{
    (void)in_sizes; (void)n_in; (void)out_size;
    const float* x    = (const float*)d_in[0];
    const float* W    = (const float*)d_in[1];
    const float* U    = (const float*)d_in[2];
    const float* bias = (const float*)d_in[3];
    const float* fc_w = (const float*)d_in[4];
    const float* fc_b = (const float*)d_in[5];

    cudaFuncSetAttribute(lstm_kernel,
                         cudaFuncAttributeMaxDynamicSharedMemorySize, SMEM_SZ);
    xsplit_kernel<<<BATCH * SEQ * IDIM / 1024, 256>>>(x);
    lstm_kernel<<<NGRP * NCTA, THREADS, SMEM_SZ>>>(W, U, bias, fc_w, fc_b, (float*)d_out);
}

// round 14
// speedup vs baseline: 1.8285x; 1.8285x over previous
#include <cuda_runtime.h>
#include <cuda_fp16.h>
#include <cstdint>

#define BATCH   64
#define SEQ     1024
#define IDIM    128
#define HDIM    512
#define G4      2048
#define KTOT    640
#define NGRP    4
#define GB      16
#define NCTA    32
#define HC      16
#define NL      64
#define THREADS 128
#define NCH_H   32
#define NCH_X   8
#define NCH     40

#define ZSTR     648
#define OFF_Z    0
#define OFF_A0   (NL * ZSTR * 2)            // 82944 : staging buf 0 (16KB)
#define OFF_A1   (OFF_A0 + NCH_H * 512)     // 99328 : staging buf 1 (16KB)
#define OFF_MBAR (OFF_A1 + NCH_H * 512)     // 115712
#define SMEM_SZ  (OFF_MBAR + 16)            // 115728 B

// ---- global scratch (static) -------------------------------------------------
__device__ uint32_t g_xfrag[(size_t)NGRP * SEQ * NCH_X * 128];  // x in frag layout
__device__ uint32_t g_hfrag[2 * NGRP * NCTA * 128];             // ping-pong h chunks
__device__ float    g_hfin[BATCH][HDIM];                        // exact final h
__device__ int      g_step[NGRP][32];                           // 128B-padded counter
__device__ int      g_cnt, g_gen;

// ---- prologue-only global barrier (replay-safe) ------------------------------
__device__ __forceinline__ void bar_all(int n)
{
    int my;
    asm volatile("ld.acquire.gpu.global.b32 %0, [%1];" : "=r"(my) : "l"(&g_gen));
    __threadfence();
    if (atomicAdd(&g_cnt, 1) == n - 1) {
        atomicExch(&g_cnt, 0);
        __threadfence();
        atomicAdd(&g_gen, 1);
    } else {
        int v;
        do { asm volatile("ld.acquire.gpu.global.b32 %0, [%1];" : "=r"(v) : "l"(&g_gen)); }
        while (v == my);
    }
}

// single-line poll + single-counter release (validated best, R6/R9)
__device__ __forceinline__ void poll_cnt(int g, int need)
{
    const int* p = &g_step[g][0];
    int v;
    do { asm volatile("ld.acquire.gpu.global.b32 %0, [%1];" : "=r"(v) : "l"(p)); }
    while (v < need);
}
__device__ __forceinline__ void release_inc(int g)
{
    asm volatile("red.add.release.gpu.global.s32 [%0], 1;" :: "l"(&g_step[g][0]) : "memory");
}

__device__ __forceinline__ void cpasync16(uint32_t dst, const void* src)
{
    asm volatile("cp.async.cg.shared.global [%0], [%1], 16;" :: "r"(dst), "l"(src));
}
// .noinc is load-bearing (R8 deadlock without it)
__device__ __forceinline__ void cp_mbar_arrive(uint32_t mbar)
{
    asm volatile("cp.async.mbarrier.arrive.noinc.shared::cta.b64 [%0];"
                 :: "r"(mbar) : "memory");
}
__device__ __forceinline__ void mbar_init(uint32_t mbar, int cnt)
{
    asm volatile("mbarrier.init.shared.b64 [%0], %1;" :: "r"(mbar), "r"(cnt) : "memory");
}
__device__ __forceinline__ void mbar_wait(uint32_t mbar, uint32_t parity)
{
    asm volatile(
        "{\n\t"
        ".reg .pred P;\n\t"
        "WAIT_%=:\n\t"
        "mbarrier.try_wait.parity.acquire.cta.shared::cta.b64 P, [%0], %1, 0x989680;\n\t"
        "@P bra.uni DONE_%=;\n\t"
        "bra.uni WAIT_%=;\n\t"
        "DONE_%=:\n\t"
        "}"
        :: "r"(mbar), "r"(parity) : "memory");
}

__device__ __forceinline__ void lds128(unsigned r[4], uint32_t a)
{
    asm volatile("ld.shared.v4.b32 {%0,%1,%2,%3}, [%4];"
                 : "=r"(r[0]), "=r"(r[1]), "=r"(r[2]), "=r"(r[3]) : "r"(a));
}
__device__ __forceinline__ void ldsm4(unsigned r[4], uint32_t a)
{
    asm volatile("ldmatrix.sync.aligned.m8n8.x4.shared.b16 {%0,%1,%2,%3}, [%4];"
                 : "=r"(r[0]), "=r"(r[1]), "=r"(r[2]), "=r"(r[3]) : "r"(a));
}
__device__ __forceinline__ void mma_f16(float* d, const unsigned* a, const unsigned* b)
{
    asm volatile(
        "mma.sync.aligned.m16n8k16.row.col.f32.f16.f16.f32 "
        "{%0,%1,%2,%3}, {%4,%5,%6,%7}, {%8,%9}, {%0,%1,%2,%3};\n"
        : "+f"(d[0]), "+f"(d[1]), "+f"(d[2]), "+f"(d[3])
        : "r"(a[0]), "r"(a[1]), "r"(a[2]), "r"(a[3]), "r"(b[0]), "r"(b[1]));
}

// fast activations: single tanh.approx MUFU each (max rel err ~2^-11,
// same order as the fp16 product quantization already in the GEMM)
__device__ __forceinline__ float ftanh_f(float x)
{
    float y;
    asm("tanh.approx.f32 %0, %1;" : "=f"(y) : "f"(x));
    return y;
}
__device__ __forceinline__ float fsig_f(float x)
{
    return fmaf(0.5f, ftanh_f(0.5f * x), 0.5f);
}

// ---- x -> fp16 fragment-ready layout (validated) -----------------------------
extern "C" __global__ void xsplit_kernel(const float* __restrict__ x)
{
    int gid = blockIdx.x * 256 + threadIdx.x;
    int i0 = (gid & 31) * 4;
    int s  = (gid >> 5) & (SEQ - 1);
    int b  = gid >> 15;
    float4 v = *(const float4*)(x + ((size_t)b * SEQ + s) * IDIM + i0);
    int bl = b & 15, grp = b >> 4;
    int kx = i0 >> 4, kl = i0 & 15;
    int lane = ((bl & 7) << 2) | ((kl & 7) >> 1);
    int j    = ((kl >> 3) << 1) | (bl >> 3);
    uint32_t u0 = (uint32_t)__half_as_ushort(__float2half(v.x)) |
                  ((uint32_t)__half_as_ushort(__float2half(v.y)) << 16);
    uint32_t u1 = (uint32_t)__half_as_ushort(__float2half(v.z)) |
                  ((uint32_t)__half_as_ushort(__float2half(v.w)) << 16);
    size_t base = (((size_t)grp * SEQ + s) * NCH_X + kx) * 128;
    g_xfrag[base + lane * 4 + j]       = u0;
    g_xfrag[base + (lane + 1) * 4 + j] = u1;
}

// ---- persistent LSTM: R9 structure exactly, fast activations -----------------
extern "C" __global__ void __launch_bounds__(THREADS, 1)
lstm_kernel(const float* __restrict__ W, const float* __restrict__ U,
            const float* __restrict__ bias,
            const float* __restrict__ fc_w, const float* __restrict__ fc_b,
            float* __restrict__ out)
{
    extern __shared__ char smem[];
    __half* zh = (__half*)(smem + OFF_Z);

    const int tid  = threadIdx.x;
    const int lane = tid & 31;
    const int warp = tid >> 5;
    const int grp  = blockIdx.x >> 5;
    const int gc   = blockIdx.x & 31;
    const int b0   = grp * GB;
    const int h0   = gc * HC;
    const uint32_t smb  = (uint32_t)__cvta_generic_to_shared(smem);
    const uint32_t mbar = smb + OFF_MBAR;

    // weights into smem, gate-interleaved local cols: nl -> hid=nl>>2, gate=nl&3
    for (int idx = tid; idx < KTOT * NL; idx += THREADS) {
        int k = idx >> 6, nl = idx & 63;
        int col = (nl & 3) * HDIM + h0 + (nl >> 2);
        float v = (k < HDIM) ? U[(size_t)k * G4 + col]
                             : W[(size_t)(k - HDIM) * G4 + col];
        zh[nl * ZSTR + k] = __float2half(v);
    }
    const int q = (lane >> 1) & 1;
    float bv[2][2];
    #pragma unroll
    for (int t = 0; t < 2; t++) {
        int hid = h0 + warp * 4 + t * 2 + q;
        #pragma unroll
        for (int j = 0; j < 2; j++)
            bv[t][j] = bias[(2 * (lane & 1) + j) * HDIM + hid];
    }
    if (tid == 0) {
        if (gc == 0) g_step[grp][0] = 0;   // replay-safe reset
        mbar_init(mbar, THREADS);
    }
    __syncthreads();

    // hoist ALL B fragments into registers (loop-invariant across 1024 steps)
    const int brow = warp * 16 + ((lane & 7) | ((lane >> 1) & 8));
    const uint32_t bHiA = smb + OFF_Z + ((brow * ZSTR + (lane & 8)) << 1);
    unsigned bfr[NCH][4];
    #pragma unroll
    for (int kc = 0; kc < NCH; kc++)
        ldsm4(bfr[kc], bHiA + kc * 32);

    if (tid == 0) bar_all(NGRP * NCTA);
    __syncthreads();

    const int r = lane >> 2;
    const int jt_c = (warp >> 1) << 1;
    const int lt_c = (warp & 1) << 1;
    float c0 = 0.f, c1 = 0.f;

    for (int s = 0; s < SEQ; s++) {
        // 4 accumulator chains: [t][even/odd]
        float accA[2][4], accB[2][4];
        #pragma unroll
        for (int t = 0; t < 2; t++) {
            accA[t][0] = bv[t][0]; accA[t][1] = bv[t][1];
            accA[t][2] = bv[t][0]; accA[t][3] = bv[t][1];
            accB[t][0] = 0.f; accB[t][1] = 0.f;
            accB[t][2] = 0.f; accB[t][3] = 0.f;
        }

        // x fragment loads (issued before the poll; latency hidden)
        uint32_t xv[NCH_X][4];
        {
            const uint4* xb = (const uint4*)(g_xfrag +
                (((size_t)grp * SEQ + s) * NCH_X) * 128 + lane * 4);
            #pragma unroll
            for (int kx = 0; kx < NCH_X; kx++) {
                uint4 t4 = __ldg(xb + kx * 32);
                xv[kx][0] = t4.x; xv[kx][1] = t4.y; xv[kx][2] = t4.z; xv[kx][3] = t4.w;
            }
        }

        const uint32_t aStg = smb + ((s & 1) ? OFF_A1 : OFF_A0) + lane * 16;

        if (s > 0) {
            poll_cnt(grp, 128 * s);
            const char* hsrc = (const char*)g_hfrag +
                ((size_t)((s & 1) * NGRP + grp) * NCTA) * 512 + lane * 16;
            #pragma unroll
            for (int i = 0; i < 8; i++) {
                int kc = warp * 8 + i;
                cpasync16(aStg + kc * 512, hsrc + kc * 512);
            }
            cp_mbar_arrive(mbar);
        }

        // x-part GEMM (regs only; overlaps cp.async flight)
        #pragma unroll
        for (int kx = 0; kx < NCH_X; kx++) {
            float* d0 = (kx & 1) ? accB[0] : accA[0];
            float* d1 = (kx & 1) ? accB[1] : accA[1];
            mma_f16(d0, xv[kx], bfr[NCH_H + kx]);
            mma_f16(d1, xv[kx], bfr[NCH_H + kx] + 2);
        }

        // h-part GEMM (after mbarrier parity wait; no syncthreads)
        if (s > 0) {
            mbar_wait(mbar, (s - 1) & 1);
            #pragma unroll
            for (int kc = 0; kc < NCH_H; kc++) {
                unsigned av[4];
                lds128(av, aStg + kc * 512);
                float* d0 = (kc & 1) ? accB[0] : accA[0];
                float* d1 = (kc & 1) ? accB[1] : accA[1];
                mma_f16(d0, av, bfr[kc]);
                mma_f16(d1, av, bfr[kc] + 2);
            }
        }

        // register epilogue: combine chains, gate exchange, packed h store
        char* hdst = (char*)g_hfrag +
            ((size_t)(((s + 1) & 1) * NGRP + grp) * NCTA + gc) * 512;
        #pragma unroll
        for (int t = 0; t < 2; t++) {
            float a0 = accA[t][0] + accB[t][0];
            float a1 = accA[t][1] + accB[t][1];
            float a2 = accA[t][2] + accB[t][2];
            float a3 = accA[t][3] + accB[t][3];
            float e0 = __shfl_xor_sync(0xffffffffu, a0, 1);
            float e1 = __shfl_xor_sync(0xffffffffu, a1, 1);
            float e2 = __shfl_xor_sync(0xffffffffu, a2, 1);
            float e3 = __shfl_xor_sync(0xffffffffu, a3, 1);
            float gi, gf, gg, go;
            int bidx;
            if ((lane & 1) == 0) {
                gi = a0; gf = a1; gg = e0; go = e1; bidx = r;
            } else {
                gi = e2; gf = e3; gg = a2; go = a3; bidx = r + 8;
            }
            float i_ = fsig_f(gi), f_ = fsig_f(gf), g_ = ftanh_f(gg), o_ = fsig_f(go);
            float& cc = t ? c1 : c0;
            cc = f_ * cc + i_ * g_;
            float h = o_ * ftanh_f(cc);
            unsigned hb = (unsigned)__half_as_ushort(__float2half(h));
            unsigned ob = __shfl_xor_sync(0xffffffffu, hb, 2);
            if (q == 0) {
                unsigned word = hb | (ob << 16);
                int lt = ((bidx & 7) << 2) | lt_c | t;
                int jt = jt_c | (bidx >> 3);
                *(unsigned*)(hdst + lt * 16 + jt * 4) = word;
            }
            if (s == SEQ - 1) g_hfin[b0 + bidx][h0 + warp * 4 + t * 2 + q] = h;
        }
        if (lane == 0) release_inc(grp);
    }

    // FC head: one CTA per group, exact fp32 h
    if (gc == 0) {
        poll_cnt(grp, 128 * SEQ);
        int b = tid >> 3, l8 = tid & 7;
        float a7[7] = {0.f, 0.f, 0.f, 0.f, 0.f, 0.f, 0.f};
        for (int it = 0; it < HDIM / 8; it++) {
            int k = l8 + it * 8;
            float hv;
            asm volatile("ld.relaxed.gpu.global.f32 %0, [%1];"
                         : "=f"(hv) : "l"(&g_hfin[b0 + b][k]));
            #pragma unroll
            for (int o = 0; o < 7; o++) a7[o] += hv * fc_w[k * 7 + o];
        }
        #pragma unroll
        for (int o = 0; o < 7; o++) {
            a7[o] += __shfl_xor_sync(0xffffffffu, a7[o], 4);
            a7[o] += __shfl_xor_sync(0xffffffffu, a7[o], 2);
            a7[o] += __shfl_xor_sync(0xffffffffu, a7[o], 1);
        }
        if (l8 == 0)
            #pragma unroll
            for (int o = 0; o < 7; o++) out[(b0 + b) * 7 + o] = a7[o] + fc_b[o];
    }
}

extern "C" void kernel_launch(void* const* d_in, const int* in_sizes, int n_in,
                              void* d_out, int out_size)
{
    (void)in_sizes; (void)n_in; (void)out_size;
    const float* x    = (const float*)d_in[0];
    const float* W    = (const float*)d_in[1];
    const float* U    = (const float*)d_in[2];
    const float* bias = (const float*)d_in[3];
    const float* fc_w = (const float*)d_in[4];
    const float* fc_b = (const float*)d_in[5];

    cudaFuncSetAttribute(lstm_kernel,
                         cudaFuncAttributeMaxDynamicSharedMemorySize, SMEM_SZ);
    xsplit_kernel<<<BATCH * SEQ * IDIM / 1024, 256>>>(x);
    lstm_kernel<<<NGRP * NCTA, THREADS, SMEM_SZ>>>(W, U, bias, fc_w, fc_b, (float*)d_out);
}